// round 13
// baseline (speedup 1.0000x reference)
#include <cuda_runtime.h>
#include <cuda_fp16.h>
#include <mma.h>
#include <math.h>

using namespace nvcuda;

#define MAXN 50000
#define PADN 50176   // 392*128, covers GEMM row tiles
#define MAXE 1600000
#define DDIM 128
#define SCB 256
#define MAXSB 256

struct __align__(8) Edge { int s; float c; };

// ---- device scratch (no allocation allowed; zero-init at module load) ----
__device__ int    g_indeg[MAXN];     // invariant: zero on kernel_launch entry
__device__ int    g_outdeg[MAXN];    // (scan_fused re-zeros after reading)
__device__ int    g_rowptr[MAXN + 1];
__device__ int    g_blocksum[MAXSB];
__device__ int    g_blockoff[MAXSB];
__device__ int    g_scancnt;         // arrival counter (reset each epoch)
__device__ volatile int g_epoch;     // monotonic epoch flag
__device__ float  g_wet[8];
__device__ float  g_sn[MAXN];     // src-side norm (prescaled into stored h~)
__device__ float  g_dn9[MAXN];    // 0.9 * dst-side norm
__device__ int    g_rank[MAXE];   // per-edge slot within its dst row
__device__ Edge   g_edges[MAXE];
__device__ __align__(16) __half g_ha[(size_t)PADN * DDIM];
__device__ __align__(16) __half g_hb[(size_t)PADN * DDIM];
__device__ __align__(16) __half g_res[(size_t)PADN * DDIM];  // 0.1*feat, half
__device__ __align__(16) __half g_w1h[DDIM * DDIM];
__device__ __align__(16) __half g_w2h[DDIM * DDIM];

// ---------------------------------------------------------------------------
// merged launch: blocks [0,HB): degree histogram (4-way ILP, rank capture)
//                blocks [HB,HB+64): W1/W2 -> half
//                block  HB+64: the 8 edge gates
__global__ void hist_gate_kernel(const int* __restrict__ src, const int* __restrict__ dst,
                                 int E, int HB,
                                 const float* __restrict__ emb,
                                 const float* __restrict__ We1, const float* __restrict__ be1,
                                 const float* __restrict__ We2, const float* __restrict__ be2,
                                 const float* __restrict__ W1,  const float* __restrict__ W2) {
    if (blockIdx.x >= (unsigned)HB) {
        int bb = blockIdx.x - HB;
        if (bb < 64) {
            int i = bb * 256 + threadIdx.x;   // 64*256 = 16384 = DDIM*DDIM
            g_w1h[i] = __float2half_rn(W1[i]);
            g_w2h[i] = __float2half_rn(W2[i]);
            return;
        }
        __shared__ float eh[8][32];
        int t = threadIdx.x;
        int et = t >> 5, j = t & 31;
        float dot = be1[j];
        #pragma unroll 8
        for (int i = 0; i < 128; i++) dot += emb[et * 128 + i] * We1[i * 32 + j];
        float g = 0.5f * dot * (1.0f + erff(dot * 0.70710678118654752f));
        eh[et][j] = g;
        __syncthreads();
        if (j == 0) {
            float d2 = be2[0];
            #pragma unroll
            for (int jj = 0; jj < 32; jj++) d2 += eh[et][jj] * We2[jj];
            float sg = 1.0f / (1.0f + expf(-d2));
            g_wet[et] = 1.0f + sg;
        }
        return;
    }

    int tid = blockIdx.x * blockDim.x + threadIdx.x;
    int T = HB * blockDim.x;
    int i0 = tid, i1 = tid + T, i2 = tid + 2 * T, i3 = tid + 3 * T;

    int s0 = 0, s1 = 0, s2 = 0, s3 = 0;
    int d0 = 0, d1 = 0, d2 = 0, d3 = 0;
    if (i0 < E) { s0 = src[i0]; d0 = dst[i0]; }
    if (i1 < E) { s1 = src[i1]; d1 = dst[i1]; }
    if (i2 < E) { s2 = src[i2]; d2 = dst[i2]; }
    if (i3 < E) { s3 = src[i3]; d3 = dst[i3]; }

    int r0 = 0, r1 = 0, r2 = 0, r3 = 0;
    if (i0 < E) { atomicAdd(&g_outdeg[s0], 1); r0 = atomicAdd(&g_indeg[d0], 1); }
    if (i1 < E) { atomicAdd(&g_outdeg[s1], 1); r1 = atomicAdd(&g_indeg[d1], 1); }
    if (i2 < E) { atomicAdd(&g_outdeg[s2], 1); r2 = atomicAdd(&g_indeg[d2], 1); }
    if (i3 < E) { atomicAdd(&g_outdeg[s3], 1); r3 = atomicAdd(&g_indeg[d3], 1); }

    if (i0 < E) g_rank[i0] = r0;
    if (i1 < E) g_rank[i1] = r1;
    if (i2 < E) g_rank[i2] = r2;
    if (i3 < E) g_rank[i3] = r3;
}

// ---------------------------------------------------------------------------
// single-kernel scan: block-inclusive scan of indeg, last-arriving block scans
// block sums, epoch flag releases everyone. Monotonic epoch: replay-safe.
__global__ void __launch_bounds__(SCB) scan_fused(int N, int NB) {
    __shared__ int s[SCB];
    __shared__ int slast;
    int b = blockIdx.x, t = threadIdx.x;
    int idx = b * SCB + t;

    int e0 = g_epoch;   // read epoch BEFORE arrival
    int v  = (idx < N) ? g_indeg[idx]  : 0;
    int od = (idx < N) ? g_outdeg[idx] : 0;

    s[t] = v; __syncthreads();
    #pragma unroll
    for (int off = 1; off < SCB; off <<= 1) {
        int x = (t >= off) ? s[t - off] : 0;
        __syncthreads();
        s[t] += x;
        __syncthreads();
    }
    int inc = s[t];

    if (t == SCB - 1) {
        g_blocksum[b] = inc;
        __threadfence();
        int arrived = atomicAdd(&g_scancnt, 1);
        slast = (arrived == NB - 1) ? 1 : 0;
    }
    __syncthreads();

    if (slast) {
        __threadfence();
        int bv = (t < NB) ? g_blocksum[t] : 0;
        s[t] = bv; __syncthreads();
        #pragma unroll
        for (int off = 1; off < SCB; off <<= 1) {
            int x = (t >= off) ? s[t - off] : 0;
            __syncthreads();
            s[t] += x;
            __syncthreads();
        }
        if (t < NB) g_blockoff[t] = s[t] - bv;
        if (t == NB - 1) g_rowptr[N] = s[t];
        __syncthreads();
        if (t == 0) {
            g_scancnt = 0;
            __threadfence();
            g_epoch = e0 + 1;
        }
    }

    if (t == 0) { while (g_epoch == e0) { } }
    __syncthreads();
    __threadfence();

    int off = g_blockoff[b];
    if (idx < N) {
        g_rowptr[idx] = off + inc - v;
        g_sn[idx]  = rsqrtf((float)max(od, 1));
        g_dn9[idx] = 0.9f * rsqrtf((float)max(v, 1));
        g_indeg[idx]  = 0;
        g_outdeg[idx] = 0;
    }
}

// ---------------------------------------------------------------------------
// merged launch: blocks [0,FB): feat -> prescaled half h~ + half residual
//                blocks [FB,...): scatter edges into CSR slots (4-way ILP)
__global__ void f2h_scatter_kernel(const float* __restrict__ feat, __half* __restrict__ h,
                                   int n4, int FB,
                                   const int* __restrict__ src, const int* __restrict__ dst,
                                   const int* __restrict__ ef, int E, int SB_) {
    if (blockIdx.x < (unsigned)FB) {
        int i = blockIdx.x * 256 + threadIdx.x;
        if (i >= n4) return;
        float4 v = ((const float4*)feat)[i];
        float sn = g_sn[i >> 5];
        __half2 a = __floats2half2_rn(sn * v.x, sn * v.y);
        __half2 b = __floats2half2_rn(sn * v.z, sn * v.w);
        uint2 o; o.x = *(unsigned*)&a; o.y = *(unsigned*)&b;
        ((uint2*)h)[i] = o;
        __half2 ra = __floats2half2_rn(0.1f * v.x, 0.1f * v.y);
        __half2 rb = __floats2half2_rn(0.1f * v.z, 0.1f * v.w);
        uint2 r; r.x = *(unsigned*)&ra; r.y = *(unsigned*)&rb;
        ((uint2*)g_res)[i] = r;
        return;
    }

    int tid = (blockIdx.x - FB) * 256 + threadIdx.x;
    int T = SB_ * 256;
    int i0 = tid, i1 = tid + T, i2 = tid + 2 * T, i3 = tid + 3 * T;

    int s0 = 0, s1 = 0, s2 = 0, s3 = 0, d0 = 0, d1 = 0, d2 = 0, d3 = 0;
    int e0 = 0, e1 = 0, e2 = 0, e3 = 0, k0 = 0, k1 = 0, k2 = 0, k3 = 0;
    if (i0 < E) { s0 = src[i0]; d0 = dst[i0]; e0 = ef[i0]; k0 = g_rank[i0]; }
    if (i1 < E) { s1 = src[i1]; d1 = dst[i1]; e1 = ef[i1]; k1 = g_rank[i1]; }
    if (i2 < E) { s2 = src[i2]; d2 = dst[i2]; e2 = ef[i2]; k2 = g_rank[i2]; }
    if (i3 < E) { s3 = src[i3]; d3 = dst[i3]; e3 = ef[i3]; k3 = g_rank[i3]; }

    float c0 = 0, c1 = 0, c2 = 0, c3 = 0;
    int p0 = 0, p1 = 0, p2 = 0, p3 = 0;
    if (i0 < E) { c0 = g_wet[e0]; p0 = g_rowptr[d0] + k0; }
    if (i1 < E) { c1 = g_wet[e1]; p1 = g_rowptr[d1] + k1; }
    if (i2 < E) { c2 = g_wet[e2]; p2 = g_rowptr[d2] + k2; }
    if (i3 < E) { c3 = g_wet[e3]; p3 = g_rowptr[d3] + k3; }

    if (i0 < E) { Edge e; e.s = s0; e.c = c0; g_edges[p0] = e; }
    if (i1 < E) { Edge e; e.s = s1; e.c = c1; g_edges[p1] = e; }
    if (i2 < E) { Edge e; e.s = s2; e.c = c2; g_edges[p2] = e; }
    if (i3 < E) { Edge e; e.s = s3; e.c = c3; g_edges[p3] = e; }
}

// ---------------------------------------------------------------------------
// one hop on prescaled h~ = sn*h: warp per dst row, lane = 4 features (8B load)
//   h'  = dn9[row] * sum_e c_e * h~[src_e] + res[row]
//   out = LAST ? h' : sn[row] * h'
// Edge broadcast via per-warp smem staging: 1 LDS.64 broadcast per edge
// (replaces 2 SHFLs; LDS address is loop-static -> issues early, no
// dependent-decode chain; arithmetic bit-identical to the shfl version)
template <bool LAST>
__global__ void __launch_bounds__(256) hop_kernel(const __half* __restrict__ hin,
                                                  __half* __restrict__ hout, int N) {
    __shared__ Edge stage[8][32];    // 2KB: one 32-edge buffer per warp

    int gw = (blockIdx.x * blockDim.x + threadIdx.x) >> 5;
    if (gw >= N) return;
    int lane = threadIdx.x & 31;
    Edge* st = stage[(threadIdx.x >> 5)];

    int beg = g_rowptr[gw];
    int end = g_rowptr[gw + 1];

    float4 acc = make_float4(0.f, 0.f, 0.f, 0.f);

    int e = beg;
    for (; e + 32 <= end; e += 32) {
        st[lane] = g_edges[e + lane];
        __syncwarp();
        #pragma unroll 8
        for (int j = 0; j < 32; ++j) {
            Edge ed = st[j];                 // LDS.64 broadcast (conflict-free)
            uint2 v = __ldg((const uint2*)(hin + (size_t)ed.s * DDIM) + lane);
            float2 f0 = __half22float2(*(__half2*)&v.x);
            float2 f1 = __half22float2(*(__half2*)&v.y);
            acc.x = fmaf(ed.c, f0.x, acc.x);
            acc.y = fmaf(ed.c, f0.y, acc.y);
            acc.z = fmaf(ed.c, f1.x, acc.z);
            acc.w = fmaf(ed.c, f1.y, acc.w);
        }
        __syncwarp();                        // drain reads before next overwrite
    }
    int n = end - e;
    if (n > 0) {
        if (lane < n) st[lane] = g_edges[e + lane];
        __syncwarp();
        for (int j = 0; j < n; ++j) {
            Edge ed = st[j];
            uint2 v = __ldg((const uint2*)(hin + (size_t)ed.s * DDIM) + lane);
            float2 f0 = __half22float2(*(__half2*)&v.x);
            float2 f1 = __half22float2(*(__half2*)&v.y);
            acc.x = fmaf(ed.c, f0.x, acc.x);
            acc.y = fmaf(ed.c, f0.y, acc.y);
            acc.z = fmaf(ed.c, f1.x, acc.z);
            acc.w = fmaf(ed.c, f1.y, acc.w);
        }
    }

    float dn9 = g_dn9[gw];
    uint2 rv = ((const uint2*)g_res)[gw * 32 + lane];
    float2 r0 = __half22float2(*(__half2*)&rv.x);
    float2 r1 = __half22float2(*(__half2*)&rv.y);
    float ox = fmaf(dn9, acc.x, r0.x);
    float oy = fmaf(dn9, acc.y, r0.y);
    float oz = fmaf(dn9, acc.z, r1.x);
    float ow = fmaf(dn9, acc.w, r1.y);
    if (!LAST) {
        float sn = g_sn[gw];
        ox *= sn; oy *= sn; oz *= sn; ow *= sn;
    }
    __half2 a = __floats2half2_rn(ox, oy);
    __half2 b = __floats2half2_rn(oz, ow);
    uint2 o; o.x = *(unsigned*)&a; o.y = *(unsigned*)&b;
    ((uint2*)hout)[gw * 32 + lane] = o;
}

// ---------------------------------------------------------------------------
// Fused output MLP: out = gelu(A@W1+b1) @ W2 + b2, tensor cores, fp32 accum.
#define EPI_LD 72   // padded row stride (floats) for per-warp epilogue scratch
__global__ void __launch_bounds__(256) mlp_kernel(const __half* __restrict__ A,
                                                  const float* __restrict__ b1,
                                                  const float* __restrict__ b2,
                                                  float* __restrict__ Out, int M) {
    extern __shared__ char smraw[];
    __half* W1s = (__half*)smraw;                    //     0..32768
    __half* W2s = (__half*)(smraw + 32768);          // 32768..65536
    __half* A2  = (__half*)(smraw + 65536);          // 65536..98304 (128x128 half)
    float*  Es  = (float*)(smraw + 98304);           // 8 * 32*EPI_LD floats

    int t = threadIdx.x, wid = t >> 5, lane = t & 31;

    {   // stage both weight matrices
        const uint4* w1 = (const uint4*)g_w1h;
        const uint4* w2 = (const uint4*)g_w2h;
        uint4* d1 = (uint4*)W1s;
        uint4* d2 = (uint4*)W2s;
        #pragma unroll
        for (int i = t; i < 2048; i += 256) { d1[i] = w1[i]; d2[i] = w2[i]; }
    }
    __syncthreads();

    int wy = wid & 3, wx = wid >> 2;
    int row0 = blockIdx.x * 128 + wy * 32;
    int lrow0 = wy * 32;
    int col0 = wx * 64;

    float* es = Es + wid * (32 * EPI_LD);

    // ---- pass 1: A @ W1 ----
    wmma::fragment<wmma::accumulator, 16, 16, 16, float> acc[2][4];
    #pragma unroll
    for (int i = 0; i < 2; i++)
        #pragma unroll
        for (int j = 0; j < 4; j++) wmma::fill_fragment(acc[i][j], 0.0f);

    #pragma unroll
    for (int kk = 0; kk < 8; kk++) {
        wmma::fragment<wmma::matrix_a, 16, 16, 16, __half, wmma::row_major> af[2];
        wmma::fragment<wmma::matrix_b, 16, 16, 16, __half, wmma::row_major> bf[4];
        #pragma unroll
        for (int i = 0; i < 2; i++)
            wmma::load_matrix_sync(af[i], A + (size_t)(row0 + i * 16) * DDIM + kk * 16, DDIM);
        #pragma unroll
        for (int j = 0; j < 4; j++)
            wmma::load_matrix_sync(bf[j], W1s + kk * 16 * DDIM + col0 + j * 16, DDIM);
        #pragma unroll
        for (int i = 0; i < 2; i++)
            #pragma unroll
            for (int j = 0; j < 4; j++)
                wmma::mma_sync(acc[i][j], af[i], bf[j], acc[i][j]);
    }

    // epilogue 1: bias + exact GELU -> half tile A2
    #pragma unroll
    for (int i = 0; i < 2; i++)
        #pragma unroll
        for (int j = 0; j < 4; j++)
            wmma::store_matrix_sync(es + i * 16 * EPI_LD + j * 16, acc[i][j],
                                    EPI_LD, wmma::mem_row_major);
    __syncwarp();
    {
        int lr = lrow0 + lane;
        #pragma unroll
        for (int c4 = 0; c4 < 16; c4++) {
            float4 v = *(float4*)&es[lane * EPI_LD + c4 * 4];
            int col = col0 + c4 * 4;
            float4 b = *(const float4*)&b1[col];
            v.x += b.x; v.y += b.y; v.z += b.z; v.w += b.w;
            v.x = 0.5f * v.x * (1.0f + erff(v.x * 0.70710678118654752f));
            v.y = 0.5f * v.y * (1.0f + erff(v.y * 0.70710678118654752f));
            v.z = 0.5f * v.z * (1.0f + erff(v.z * 0.70710678118654752f));
            v.w = 0.5f * v.w * (1.0f + erff(v.w * 0.70710678118654752f));
            __half2 h0 = __floats2half2_rn(v.x, v.y);
            __half2 h1 = __floats2half2_rn(v.z, v.w);
            uint2 o; o.x = *(unsigned*)&h0; o.y = *(unsigned*)&h1;
            *(uint2*)&A2[(size_t)lr * DDIM + col] = o;
        }
    }
    __syncthreads();

    // ---- pass 2: gelu-tile @ W2 ----
    #pragma unroll
    for (int i = 0; i < 2; i++)
        #pragma unroll
        for (int j = 0; j < 4; j++) wmma::fill_fragment(acc[i][j], 0.0f);

    #pragma unroll
    for (int kk = 0; kk < 8; kk++) {
        wmma::fragment<wmma::matrix_a, 16, 16, 16, __half, wmma::row_major> af[2];
        wmma::fragment<wmma::matrix_b, 16, 16, 16, __half, wmma::row_major> bf[4];
        #pragma unroll
        for (int i = 0; i < 2; i++)
            wmma::load_matrix_sync(af[i], A2 + (size_t)(lrow0 + i * 16) * DDIM + kk * 16, DDIM);
        #pragma unroll
        for (int j = 0; j < 4; j++)
            wmma::load_matrix_sync(bf[j], W2s + kk * 16 * DDIM + col0 + j * 16, DDIM);
        #pragma unroll
        for (int i = 0; i < 2; i++)
            #pragma unroll
            for (int j = 0; j < 4; j++)
                wmma::mma_sync(acc[i][j], af[i], bf[j], acc[i][j]);
    }

    // epilogue 2: bias -> fp32 out
    #pragma unroll
    for (int i = 0; i < 2; i++)
        #pragma unroll
        for (int j = 0; j < 4; j++)
            wmma::store_matrix_sync(es + i * 16 * EPI_LD + j * 16, acc[i][j],
                                    EPI_LD, wmma::mem_row_major);
    __syncwarp();
    {
        int grow = row0 + lane;
        if (grow < M) {
            #pragma unroll
            for (int c4 = 0; c4 < 16; c4++) {
                float4 v = *(float4*)&es[lane * EPI_LD + c4 * 4];
                int col = col0 + c4 * 4;
                float4 b = *(const float4*)&b2[col];
                v.x += b.x; v.y += b.y; v.z += b.z; v.w += b.w;
                *(float4*)&Out[(size_t)grow * DDIM + col] = v;
            }
        }
    }
}

// ---------------------------------------------------------------------------
extern "C" void kernel_launch(void* const* d_in, const int* in_sizes, int n_in,
                              void* d_out, int out_size) {
    const float* feat = (const float*)d_in[0];
    const int*   ef   = (const int*)d_in[1];
    const int*   src  = (const int*)d_in[2];
    const int*   dst  = (const int*)d_in[3];
    const float* emb  = (const float*)d_in[4];
    const float* We1  = (const float*)d_in[5];
    const float* be1  = (const float*)d_in[6];
    const float* We2  = (const float*)d_in[7];
    const float* be2  = (const float*)d_in[8];
    const float* W1   = (const float*)d_in[9];
    const float* b1   = (const float*)d_in[10];
    const float* W2   = (const float*)d_in[11];
    const float* b2   = (const float*)d_in[12];
    float* out = (float*)d_out;

    int N = in_sizes[0] / DDIM;   // 50000
    int E = in_sizes[1];          // 1600000

    void *pa = nullptr, *pb = nullptr;
    cudaGetSymbolAddress(&pa, g_ha);
    cudaGetSymbolAddress(&pb, g_hb);
    __half* ha  = (__half*)pa;
    __half* hb  = (__half*)pb;

    const int MLP_SMEM = 98304 + 8 * 32 * EPI_LD * 4;   // 172032
    cudaFuncSetAttribute(mlp_kernel, cudaFuncAttributeMaxDynamicSharedMemorySize, MLP_SMEM);

    // --- build phase ---
    int qthreads = (E + 3) / 4;
    int HB = (qthreads + 255) / 256;      // 1563 hist blocks
    hist_gate_kernel<<<HB + 65, 256>>>(src, dst, E, HB,
                                       emb, We1, be1, We2, be2, W1, W2);
    int NB = (N + SCB - 1) / SCB;         // 196
    scan_fused<<<NB, SCB>>>(N, NB);

    int n4 = N * DDIM / 4;
    int FB = (n4 + 255) / 256;            // 6250 f2h blocks
    f2h_scatter_kernel<<<FB + HB, 256>>>(feat, ha, n4, FB, src, dst, ef, E, HB);

    // --- K=10 propagation hops (half ping-pong; hop 9 lands in ha, unscaled) ---
    int hop_blocks = (N * 32 + 255) / 256;
    for (int k = 0; k < 9; k++) {
        const __half* hin  = (k & 1) ? hb : ha;
        __half*       hout = (k & 1) ? ha : hb;
        hop_kernel<false><<<hop_blocks, 256>>>(hin, hout, N);
    }
    hop_kernel<true><<<hop_blocks, 256>>>(hb, ha, N);

    // --- fused output MLP (tensor cores) ---
    int gblocks = PADN / 128;   // 392
    mlp_kernel<<<gblocks, 256, MLP_SMEM>>>(ha, b1, b2, out, N);
}

// round 14
// speedup vs baseline: 1.4087x; 1.4087x over previous
#include <cuda_runtime.h>
#include <cuda_fp16.h>
#include <mma.h>
#include <math.h>

using namespace nvcuda;

#define MAXN 50000
#define PADN 50176   // 392*128, covers GEMM row tiles
#define MAXE 1600000
#define DDIM 128
#define SCB 256
#define MAXSB 256

struct __align__(8) Edge { int s; float c; };

// ---- device scratch (no allocation allowed; zero-init at module load) ----
__device__ int    g_indeg[MAXN];     // invariant: zero on kernel_launch entry
__device__ int    g_outdeg[MAXN];    // (scan_fused re-zeros after reading)
__device__ int    g_rowptr[MAXN + 1];
__device__ int    g_blocksum[MAXSB];
__device__ int    g_blockoff[MAXSB];
__device__ int    g_scancnt;         // arrival counter (reset each epoch)
__device__ volatile int g_epoch;     // monotonic epoch flag
__device__ float  g_wet[8];
__device__ float  g_sn[MAXN];     // src-side norm (prescaled into stored h~)
__device__ float  g_dn9[MAXN];    // 0.9 * dst-side norm
__device__ int    g_rank[MAXE];   // per-edge slot within its dst row
__device__ Edge   g_edges[MAXE];
__device__ __align__(16) __half g_ha[(size_t)PADN * DDIM];
__device__ __align__(16) __half g_hb[(size_t)PADN * DDIM];
__device__ __align__(16) __half g_res[(size_t)PADN * DDIM];  // 0.1*feat, half
__device__ __align__(16) __half g_w1h[DDIM * DDIM];
__device__ __align__(16) __half g_w2h[DDIM * DDIM];

// ---------------------------------------------------------------------------
// merged launch: blocks [0,HB): degree histogram (4-way ILP, rank capture)
//                blocks [HB,HB+64): W1/W2 -> half
//                block  HB+64: the 8 edge gates
__global__ void hist_gate_kernel(const int* __restrict__ src, const int* __restrict__ dst,
                                 int E, int HB,
                                 const float* __restrict__ emb,
                                 const float* __restrict__ We1, const float* __restrict__ be1,
                                 const float* __restrict__ We2, const float* __restrict__ be2,
                                 const float* __restrict__ W1,  const float* __restrict__ W2) {
    if (blockIdx.x >= (unsigned)HB) {
        int bb = blockIdx.x - HB;
        if (bb < 64) {
            int i = bb * 256 + threadIdx.x;   // 64*256 = 16384 = DDIM*DDIM
            g_w1h[i] = __float2half_rn(W1[i]);
            g_w2h[i] = __float2half_rn(W2[i]);
            return;
        }
        __shared__ float eh[8][32];
        int t = threadIdx.x;
        int et = t >> 5, j = t & 31;
        float dot = be1[j];
        #pragma unroll 8
        for (int i = 0; i < 128; i++) dot += emb[et * 128 + i] * We1[i * 32 + j];
        float g = 0.5f * dot * (1.0f + erff(dot * 0.70710678118654752f));
        eh[et][j] = g;
        __syncthreads();
        if (j == 0) {
            float d2 = be2[0];
            #pragma unroll
            for (int jj = 0; jj < 32; jj++) d2 += eh[et][jj] * We2[jj];
            float sg = 1.0f / (1.0f + expf(-d2));
            g_wet[et] = 1.0f + sg;
        }
        return;
    }

    int tid = blockIdx.x * blockDim.x + threadIdx.x;
    int T = HB * blockDim.x;
    int i0 = tid, i1 = tid + T, i2 = tid + 2 * T, i3 = tid + 3 * T;

    int s0 = 0, s1 = 0, s2 = 0, s3 = 0;
    int d0 = 0, d1 = 0, d2 = 0, d3 = 0;
    if (i0 < E) { s0 = src[i0]; d0 = dst[i0]; }
    if (i1 < E) { s1 = src[i1]; d1 = dst[i1]; }
    if (i2 < E) { s2 = src[i2]; d2 = dst[i2]; }
    if (i3 < E) { s3 = src[i3]; d3 = dst[i3]; }

    int r0 = 0, r1 = 0, r2 = 0, r3 = 0;
    if (i0 < E) { atomicAdd(&g_outdeg[s0], 1); r0 = atomicAdd(&g_indeg[d0], 1); }
    if (i1 < E) { atomicAdd(&g_outdeg[s1], 1); r1 = atomicAdd(&g_indeg[d1], 1); }
    if (i2 < E) { atomicAdd(&g_outdeg[s2], 1); r2 = atomicAdd(&g_indeg[d2], 1); }
    if (i3 < E) { atomicAdd(&g_outdeg[s3], 1); r3 = atomicAdd(&g_indeg[d3], 1); }

    if (i0 < E) g_rank[i0] = r0;
    if (i1 < E) g_rank[i1] = r1;
    if (i2 < E) g_rank[i2] = r2;
    if (i3 < E) g_rank[i3] = r3;
}

// ---------------------------------------------------------------------------
// single-kernel scan: block-inclusive scan of indeg, last-arriving block scans
// block sums, epoch flag releases everyone. Monotonic epoch: replay-safe.
__global__ void __launch_bounds__(SCB) scan_fused(int N, int NB) {
    __shared__ int s[SCB];
    __shared__ int slast;
    int b = blockIdx.x, t = threadIdx.x;
    int idx = b * SCB + t;

    int e0 = g_epoch;   // read epoch BEFORE arrival
    int v  = (idx < N) ? g_indeg[idx]  : 0;
    int od = (idx < N) ? g_outdeg[idx] : 0;

    s[t] = v; __syncthreads();
    #pragma unroll
    for (int off = 1; off < SCB; off <<= 1) {
        int x = (t >= off) ? s[t - off] : 0;
        __syncthreads();
        s[t] += x;
        __syncthreads();
    }
    int inc = s[t];

    if (t == SCB - 1) {
        g_blocksum[b] = inc;
        __threadfence();
        int arrived = atomicAdd(&g_scancnt, 1);
        slast = (arrived == NB - 1) ? 1 : 0;
    }
    __syncthreads();

    if (slast) {
        __threadfence();
        int bv = (t < NB) ? g_blocksum[t] : 0;
        s[t] = bv; __syncthreads();
        #pragma unroll
        for (int off = 1; off < SCB; off <<= 1) {
            int x = (t >= off) ? s[t - off] : 0;
            __syncthreads();
            s[t] += x;
            __syncthreads();
        }
        if (t < NB) g_blockoff[t] = s[t] - bv;
        if (t == NB - 1) g_rowptr[N] = s[t];
        __syncthreads();
        if (t == 0) {
            g_scancnt = 0;
            __threadfence();
            g_epoch = e0 + 1;
        }
    }

    if (t == 0) { while (g_epoch == e0) { } }
    __syncthreads();
    __threadfence();

    int off = g_blockoff[b];
    if (idx < N) {
        g_rowptr[idx] = off + inc - v;
        g_sn[idx]  = rsqrtf((float)max(od, 1));
        g_dn9[idx] = 0.9f * rsqrtf((float)max(v, 1));
        g_indeg[idx]  = 0;
        g_outdeg[idx] = 0;
    }
}

// ---------------------------------------------------------------------------
// merged launch: blocks [0,FB): feat -> prescaled half h~ + half residual
//                blocks [FB,...): scatter edges into CSR slots (4-way ILP)
__global__ void f2h_scatter_kernel(const float* __restrict__ feat, __half* __restrict__ h,
                                   int n4, int FB,
                                   const int* __restrict__ src, const int* __restrict__ dst,
                                   const int* __restrict__ ef, int E, int SB_) {
    if (blockIdx.x < (unsigned)FB) {
        int i = blockIdx.x * 256 + threadIdx.x;
        if (i >= n4) return;
        float4 v = ((const float4*)feat)[i];
        float sn = g_sn[i >> 5];
        __half2 a = __floats2half2_rn(sn * v.x, sn * v.y);
        __half2 b = __floats2half2_rn(sn * v.z, sn * v.w);
        uint2 o; o.x = *(unsigned*)&a; o.y = *(unsigned*)&b;
        ((uint2*)h)[i] = o;
        __half2 ra = __floats2half2_rn(0.1f * v.x, 0.1f * v.y);
        __half2 rb = __floats2half2_rn(0.1f * v.z, 0.1f * v.w);
        uint2 r; r.x = *(unsigned*)&ra; r.y = *(unsigned*)&rb;
        ((uint2*)g_res)[i] = r;
        return;
    }

    int tid = (blockIdx.x - FB) * 256 + threadIdx.x;
    int T = SB_ * 256;
    int i0 = tid, i1 = tid + T, i2 = tid + 2 * T, i3 = tid + 3 * T;

    int s0 = 0, s1 = 0, s2 = 0, s3 = 0, d0 = 0, d1 = 0, d2 = 0, d3 = 0;
    int e0 = 0, e1 = 0, e2 = 0, e3 = 0, k0 = 0, k1 = 0, k2 = 0, k3 = 0;
    if (i0 < E) { s0 = src[i0]; d0 = dst[i0]; e0 = ef[i0]; k0 = g_rank[i0]; }
    if (i1 < E) { s1 = src[i1]; d1 = dst[i1]; e1 = ef[i1]; k1 = g_rank[i1]; }
    if (i2 < E) { s2 = src[i2]; d2 = dst[i2]; e2 = ef[i2]; k2 = g_rank[i2]; }
    if (i3 < E) { s3 = src[i3]; d3 = dst[i3]; e3 = ef[i3]; k3 = g_rank[i3]; }

    float c0 = 0, c1 = 0, c2 = 0, c3 = 0;
    int p0 = 0, p1 = 0, p2 = 0, p3 = 0;
    if (i0 < E) { c0 = g_wet[e0]; p0 = g_rowptr[d0] + k0; }
    if (i1 < E) { c1 = g_wet[e1]; p1 = g_rowptr[d1] + k1; }
    if (i2 < E) { c2 = g_wet[e2]; p2 = g_rowptr[d2] + k2; }
    if (i3 < E) { c3 = g_wet[e3]; p3 = g_rowptr[d3] + k3; }

    if (i0 < E) { Edge e; e.s = s0; e.c = c0; g_edges[p0] = e; }
    if (i1 < E) { Edge e; e.s = s1; e.c = c1; g_edges[p1] = e; }
    if (i2 < E) { Edge e; e.s = s2; e.c = c2; g_edges[p2] = e; }
    if (i3 < E) { Edge e; e.s = s3; e.c = c3; g_edges[p3] = e; }
}

// ---------------------------------------------------------------------------
// one hop on prescaled h~ = sn*h: warp per dst row, lane = 4 features (8B load)
//   h'  = dn9[row] * sum_e c_e * h~[src_e] + res[row]
//   out = LAST ? h' : sn[row] * h'
// Edge {s, c} load -> two INDEPENDENT shfls (no dependent chain before the LDG)
template <bool LAST>
__global__ void __launch_bounds__(256) hop_kernel(const __half* __restrict__ hin,
                                                  __half* __restrict__ hout, int N) {
    int gw = (blockIdx.x * blockDim.x + threadIdx.x) >> 5;
    if (gw >= N) return;
    int lane = threadIdx.x & 31;

    int beg = g_rowptr[gw];
    int end = g_rowptr[gw + 1];

    float4 acc = make_float4(0.f, 0.f, 0.f, 0.f);

    int e = beg;
    for (; e + 32 <= end; e += 32) {
        Edge ed = g_edges[e + lane];
        int   es = ed.s;
        float ec = ed.c;
        #pragma unroll 8
        for (int j = 0; j < 32; ++j) {
            int   s = __shfl_sync(0xffffffffu, es, j);
            float c = __shfl_sync(0xffffffffu, ec, j);
            uint2 v = __ldg((const uint2*)(hin + (size_t)s * DDIM) + lane);
            float2 f0 = __half22float2(*(__half2*)&v.x);
            float2 f1 = __half22float2(*(__half2*)&v.y);
            acc.x = fmaf(c, f0.x, acc.x);
            acc.y = fmaf(c, f0.y, acc.y);
            acc.z = fmaf(c, f1.x, acc.z);
            acc.w = fmaf(c, f1.y, acc.w);
        }
    }
    int n = end - e;
    if (n > 0) {
        int   es = 0;
        float ec = 0.f;
        if (lane < n) {
            Edge ed = g_edges[e + lane];
            es = ed.s; ec = ed.c;
        }
        for (int j = 0; j < n; ++j) {
            int   s = __shfl_sync(0xffffffffu, es, j);
            float c = __shfl_sync(0xffffffffu, ec, j);
            uint2 v = __ldg((const uint2*)(hin + (size_t)s * DDIM) + lane);
            float2 f0 = __half22float2(*(__half2*)&v.x);
            float2 f1 = __half22float2(*(__half2*)&v.y);
            acc.x = fmaf(c, f0.x, acc.x);
            acc.y = fmaf(c, f0.y, acc.y);
            acc.z = fmaf(c, f1.x, acc.z);
            acc.w = fmaf(c, f1.y, acc.w);
        }
    }

    float dn9 = g_dn9[gw];
    uint2 rv = ((const uint2*)g_res)[gw * 32 + lane];
    float2 r0 = __half22float2(*(__half2*)&rv.x);
    float2 r1 = __half22float2(*(__half2*)&rv.y);
    float ox = fmaf(dn9, acc.x, r0.x);
    float oy = fmaf(dn9, acc.y, r0.y);
    float oz = fmaf(dn9, acc.z, r1.x);
    float ow = fmaf(dn9, acc.w, r1.y);
    if (!LAST) {
        float sn = g_sn[gw];
        ox *= sn; oy *= sn; oz *= sn; ow *= sn;
    }
    __half2 a = __floats2half2_rn(ox, oy);
    __half2 b = __floats2half2_rn(oz, ow);
    uint2 o; o.x = *(unsigned*)&a; o.y = *(unsigned*)&b;
    ((uint2*)hout)[gw * 32 + lane] = o;
}

// ---------------------------------------------------------------------------
// Fused output MLP: out = gelu(A@W1+b1) @ W2 + b2, tensor cores, fp32 accum.
#define EPI_LD 72   // padded row stride (floats) for per-warp epilogue scratch
__global__ void __launch_bounds__(256) mlp_kernel(const __half* __restrict__ A,
                                                  const float* __restrict__ b1,
                                                  const float* __restrict__ b2,
                                                  float* __restrict__ Out, int M) {
    extern __shared__ char smraw[];
    __half* W1s = (__half*)smraw;                    //     0..32768
    __half* W2s = (__half*)(smraw + 32768);          // 32768..65536
    __half* A2  = (__half*)(smraw + 65536);          // 65536..98304 (128x128 half)
    float*  Es  = (float*)(smraw + 98304);           // 8 * 32*EPI_LD floats

    int t = threadIdx.x, wid = t >> 5, lane = t & 31;

    {   // stage both weight matrices
        const uint4* w1 = (const uint4*)g_w1h;
        const uint4* w2 = (const uint4*)g_w2h;
        uint4* d1 = (uint4*)W1s;
        uint4* d2 = (uint4*)W2s;
        #pragma unroll
        for (int i = t; i < 2048; i += 256) { d1[i] = w1[i]; d2[i] = w2[i]; }
    }
    __syncthreads();

    int wy = wid & 3, wx = wid >> 2;
    int row0 = blockIdx.x * 128 + wy * 32;
    int lrow0 = wy * 32;
    int col0 = wx * 64;

    float* es = Es + wid * (32 * EPI_LD);

    // ---- pass 1: A @ W1 ----
    wmma::fragment<wmma::accumulator, 16, 16, 16, float> acc[2][4];
    #pragma unroll
    for (int i = 0; i < 2; i++)
        #pragma unroll
        for (int j = 0; j < 4; j++) wmma::fill_fragment(acc[i][j], 0.0f);

    #pragma unroll
    for (int kk = 0; kk < 8; kk++) {
        wmma::fragment<wmma::matrix_a, 16, 16, 16, __half, wmma::row_major> af[2];
        wmma::fragment<wmma::matrix_b, 16, 16, 16, __half, wmma::row_major> bf[4];
        #pragma unroll
        for (int i = 0; i < 2; i++)
            wmma::load_matrix_sync(af[i], A + (size_t)(row0 + i * 16) * DDIM + kk * 16, DDIM);
        #pragma unroll
        for (int j = 0; j < 4; j++)
            wmma::load_matrix_sync(bf[j], W1s + kk * 16 * DDIM + col0 + j * 16, DDIM);
        #pragma unroll
        for (int i = 0; i < 2; i++)
            #pragma unroll
            for (int j = 0; j < 4; j++)
                wmma::mma_sync(acc[i][j], af[i], bf[j], acc[i][j]);
    }

    // epilogue 1: bias + exact GELU -> half tile A2
    #pragma unroll
    for (int i = 0; i < 2; i++)
        #pragma unroll
        for (int j = 0; j < 4; j++)
            wmma::store_matrix_sync(es + i * 16 * EPI_LD + j * 16, acc[i][j],
                                    EPI_LD, wmma::mem_row_major);
    __syncwarp();
    {
        int lr = lrow0 + lane;
        #pragma unroll
        for (int c4 = 0; c4 < 16; c4++) {
            float4 v = *(float4*)&es[lane * EPI_LD + c4 * 4];
            int col = col0 + c4 * 4;
            float4 b = *(const float4*)&b1[col];
            v.x += b.x; v.y += b.y; v.z += b.z; v.w += b.w;
            v.x = 0.5f * v.x * (1.0f + erff(v.x * 0.70710678118654752f));
            v.y = 0.5f * v.y * (1.0f + erff(v.y * 0.70710678118654752f));
            v.z = 0.5f * v.z * (1.0f + erff(v.z * 0.70710678118654752f));
            v.w = 0.5f * v.w * (1.0f + erff(v.w * 0.70710678118654752f));
            __half2 h0 = __floats2half2_rn(v.x, v.y);
            __half2 h1 = __floats2half2_rn(v.z, v.w);
            uint2 o; o.x = *(unsigned*)&h0; o.y = *(unsigned*)&h1;
            *(uint2*)&A2[(size_t)lr * DDIM + col] = o;
        }
    }
    __syncthreads();

    // ---- pass 2: gelu-tile @ W2 ----
    #pragma unroll
    for (int i = 0; i < 2; i++)
        #pragma unroll
        for (int j = 0; j < 4; j++) wmma::fill_fragment(acc[i][j], 0.0f);

    #pragma unroll
    for (int kk = 0; kk < 8; kk++) {
        wmma::fragment<wmma::matrix_a, 16, 16, 16, __half, wmma::row_major> af[2];
        wmma::fragment<wmma::matrix_b, 16, 16, 16, __half, wmma::row_major> bf[4];
        #pragma unroll
        for (int i = 0; i < 2; i++)
            wmma::load_matrix_sync(af[i], A2 + (size_t)(lrow0 + i * 16) * DDIM + kk * 16, DDIM);
        #pragma unroll
        for (int j = 0; j < 4; j++)
            wmma::load_matrix_sync(bf[j], W2s + kk * 16 * DDIM + col0 + j * 16, DDIM);
        #pragma unroll
        for (int i = 0; i < 2; i++)
            #pragma unroll
            for (int j = 0; j < 4; j++)
                wmma::mma_sync(acc[i][j], af[i], bf[j], acc[i][j]);
    }

    // epilogue 2: bias -> fp32 out
    #pragma unroll
    for (int i = 0; i < 2; i++)
        #pragma unroll
        for (int j = 0; j < 4; j++)
            wmma::store_matrix_sync(es + i * 16 * EPI_LD + j * 16, acc[i][j],
                                    EPI_LD, wmma::mem_row_major);
    __syncwarp();
    {
        int grow = row0 + lane;
        if (grow < M) {
            #pragma unroll
            for (int c4 = 0; c4 < 16; c4++) {
                float4 v = *(float4*)&es[lane * EPI_LD + c4 * 4];
                int col = col0 + c4 * 4;
                float4 b = *(const float4*)&b2[col];
                v.x += b.x; v.y += b.y; v.z += b.z; v.w += b.w;
                *(float4*)&Out[(size_t)grow * DDIM + col] = v;
            }
        }
    }
}

// ---------------------------------------------------------------------------
extern "C" void kernel_launch(void* const* d_in, const int* in_sizes, int n_in,
                              void* d_out, int out_size) {
    const float* feat = (const float*)d_in[0];
    const int*   ef   = (const int*)d_in[1];
    const int*   src  = (const int*)d_in[2];
    const int*   dst  = (const int*)d_in[3];
    const float* emb  = (const float*)d_in[4];
    const float* We1  = (const float*)d_in[5];
    const float* be1  = (const float*)d_in[6];
    const float* We2  = (const float*)d_in[7];
    const float* be2  = (const float*)d_in[8];
    const float* W1   = (const float*)d_in[9];
    const float* b1   = (const float*)d_in[10];
    const float* W2   = (const float*)d_in[11];
    const float* b2   = (const float*)d_in[12];
    float* out = (float*)d_out;

    int N = in_sizes[0] / DDIM;   // 50000
    int E = in_sizes[1];          // 1600000

    void *pa = nullptr, *pb = nullptr;
    cudaGetSymbolAddress(&pa, g_ha);
    cudaGetSymbolAddress(&pb, g_hb);
    __half* ha  = (__half*)pa;
    __half* hb  = (__half*)pb;

    const int MLP_SMEM = 98304 + 8 * 32 * EPI_LD * 4;   // 172032
    cudaFuncSetAttribute(mlp_kernel, cudaFuncAttributeMaxDynamicSharedMemorySize, MLP_SMEM);

    // --- build phase ---
    int qthreads = (E + 3) / 4;
    int HB = (qthreads + 255) / 256;      // 1563 hist blocks
    hist_gate_kernel<<<HB + 65, 256>>>(src, dst, E, HB,
                                       emb, We1, be1, We2, be2, W1, W2);
    int NB = (N + SCB - 1) / SCB;         // 196
    scan_fused<<<NB, SCB>>>(N, NB);

    int n4 = N * DDIM / 4;
    int FB = (n4 + 255) / 256;            // 6250 f2h blocks
    f2h_scatter_kernel<<<FB + HB, 256>>>(feat, ha, n4, FB, src, dst, ef, E, HB);

    // --- K=10 propagation hops (half ping-pong; hop 9 lands in ha, unscaled) ---
    int hop_blocks = (N * 32 + 255) / 256;
    for (int k = 0; k < 9; k++) {
        const __half* hin  = (k & 1) ? hb : ha;
        __half*       hout = (k & 1) ? ha : hb;
        hop_kernel<false><<<hop_blocks, 256>>>(hin, hout, N);
    }
    hop_kernel<true><<<hop_blocks, 256>>>(hb, ha, N);

    // --- fused output MLP (tensor cores) ---
    int gblocks = PADN / 128;   // 392
    mlp_kernel<<<gblocks, 256, MLP_SMEM>>>(ha, b1, b2, out, N);
}